// round 16
// baseline (speedup 1.0000x reference)
#include <cuda_runtime.h>
#include <cuda_bf16.h>
#include <math.h>
#include <stdint.h>

#define N_   4
#define T_   2048
#define D_   1024
#define H_   16
#define DH_  64
#define CAP_ 30.0f
#define EPS_ 1e-5f
#define ROWS_ (N_ * T_)          // 8192
#define GK_  1024

// ---------------- scratch (device globals: allocation-free) ----------------
__device__ float g_q[(size_t)ROWS_ * H_ * DH_];
__device__ float g_k[(size_t)ROWS_ * H_ * DH_];
__device__ float g_v[(size_t)ROWS_ * H_ * DH_];
__device__ __nv_bfloat16 g_ahi[(size_t)ROWS_ * GK_];
__device__ __nv_bfloat16 g_alo[(size_t)ROWS_ * GK_];
__device__ __nv_bfloat16 g_whi[(size_t)3 * GK_ * GK_];   // W^T hi: QKV segments [3072,1024]
__device__ __nv_bfloat16 g_wlo[(size_t)3 * GK_ * GK_];
// attention operands, head-major
__device__ __nv_bfloat16 g_qh[(size_t)ROWS_ * GK_];  // [b][h][t][64]
__device__ __nv_bfloat16 g_ql[(size_t)ROWS_ * GK_];
__device__ __nv_bfloat16 g_kh[(size_t)ROWS_ * GK_];
__device__ __nv_bfloat16 g_kl[(size_t)ROWS_ * GK_];
__device__ __nv_bfloat16 g_vth[(size_t)ROWS_ * GK_]; // [b][h][64][t]  (V transposed)
__device__ __nv_bfloat16 g_vtl[(size_t)ROWS_ * GK_];

// ---------------- helpers ----------------
__device__ __forceinline__ uint32_t smem_u32(const void* p) {
    uint32_t a;
    asm("{ .reg .u64 t; cvta.to.shared.u64 t, %1; cvt.u32.u64 %0, t; }" : "=r"(a) : "l"(p));
    return a;
}
__device__ __forceinline__ float fast_tanh(float x) {
    asm("tanh.approx.f32 %0, %0;" : "+f"(x));
    return x;
}
#define LDSM4(r, a)                                                           \
    asm volatile("ldmatrix.sync.aligned.m8n8.x4.shared.b16 {%0,%1,%2,%3}, [%4];" \
                 : "=r"((r)[0]), "=r"((r)[1]), "=r"((r)[2]), "=r"((r)[3]) : "r"(a))
#define CP16(sa, gp) asm volatile("cp.async.cg.shared.global [%0], [%1], 16;" :: "r"(sa), "l"(gp))
#define CPCOMMIT() asm volatile("cp.async.commit_group;" ::: "memory")
#define CPWAIT(n)  asm volatile("cp.async.wait_group %0;" :: "n"(n) : "memory")

__device__ __forceinline__ void mma16816(float* c, const uint32_t* a, const uint32_t* b) {
    asm volatile(
        "mma.sync.aligned.m16n8k16.row.col.f32.bf16.bf16.f32 "
        "{%0,%1,%2,%3}, {%4,%5,%6,%7}, {%8,%9}, {%0,%1,%2,%3};"
        : "+f"(c[0]), "+f"(c[1]), "+f"(c[2]), "+f"(c[3])
        : "r"(a[0]), "r"(a[1]), "r"(a[2]), "r"(a[3]), "r"(b[0]), "r"(b[1]));
}
__device__ __forceinline__ uint32_t pack_bf2(float p0, float p1) {
    uint32_t r;
    asm("cvt.rn.bf16x2.f32 %0, %1, %2;" : "=r"(r) : "f"(p1), "f"(p0));
    return r;
}
__device__ __forceinline__ uint32_t pack_res(uint32_t hi, float p0, float p1) {
    float h0 = __uint_as_float(hi << 16);
    float h1 = __uint_as_float(hi & 0xFFFF0000u);
    return pack_bf2(p0 - h0, p1 - h1);
}

// ---------------- LayerNorm fused with hi/lo split ----------------
__global__ void ln_split_kernel(const float* __restrict__ x, const float* __restrict__ gw,
                                const float* __restrict__ bw,
                                __nv_bfloat16* __restrict__ hi, __nv_bfloat16* __restrict__ lo) {
    __shared__ float red[8];
    __shared__ float stat[2];
    const int row = blockIdx.x;
    const int t = threadIdx.x;            // 256 threads, 4 consecutive cols each
    const float4 v = ((const float4*)(x + (size_t)row * D_))[t];
    float s = v.x + v.y + v.z + v.w;
#pragma unroll
    for (int o = 16; o; o >>= 1) s += __shfl_xor_sync(0xffffffffu, s, o);
    if ((t & 31) == 0) red[t >> 5] = s;
    __syncthreads();
    if (t == 0) {
        float tot = 0.f;
#pragma unroll
        for (int i = 0; i < 8; i++) tot += red[i];
        stat[0] = tot * (1.f / D_);
    }
    __syncthreads();
    const float mean = stat[0];
    float d0 = v.x - mean, d1 = v.y - mean, d2 = v.z - mean, d3 = v.w - mean;
    float ss = d0 * d0 + d1 * d1 + d2 * d2 + d3 * d3;
#pragma unroll
    for (int o = 16; o; o >>= 1) ss += __shfl_xor_sync(0xffffffffu, ss, o);
    if ((t & 31) == 0) red[t >> 5] = ss;
    __syncthreads();
    if (t == 0) {
        float tot = 0.f;
#pragma unroll
        for (int i = 0; i < 8; i++) tot += red[i];
        stat[1] = rsqrtf(tot * (1.f / D_) + EPS_);
    }
    __syncthreads();
    const float rs = stat[1];
    const float4 gv = ((const float4*)gw)[t];
    const float4 bv = ((const float4*)bw)[t];
    float y0 = d0 * rs * gv.x + bv.x;
    float y1 = d1 * rs * gv.y + bv.y;
    float y2 = d2 * rs * gv.z + bv.z;
    float y3 = d3 * rs * gv.w + bv.w;
    uint32_t h0 = pack_bf2(y0, y1), h1 = pack_bf2(y2, y3);
    size_t bidx = ((size_t)row * D_ + t * 4) >> 1;
    ((uint32_t*)hi)[bidx] = h0;
    ((uint32_t*)hi)[bidx + 1] = h1;
    ((uint32_t*)lo)[bidx] = pack_res(h0, y0, y1);
    ((uint32_t*)lo)[bidx + 1] = pack_res(h1, y2, y3);
}

// ---------------- transpose + split: W[K,N] fp32 -> W^T hi/lo bf16 [N,K] ----------------
__global__ void transpose_split_kernel(const float* __restrict__ W,
                                       __nv_bfloat16* __restrict__ hi,
                                       __nv_bfloat16* __restrict__ lo) {
    __shared__ float tile[32][33];
    const int k0 = blockIdx.y * 32, n0 = blockIdx.x * 32;
    const int tx = threadIdx.x, ty = threadIdx.y;        // (32, 8)
#pragma unroll
    for (int i = ty; i < 32; i += 8)
        tile[i][tx] = W[(size_t)(k0 + i) * GK_ + n0 + tx];
    __syncthreads();
#pragma unroll
    for (int i = ty; i < 32; i += 8) {
        float v = tile[tx][i];
        __nv_bfloat16 h = __float2bfloat16(v);
        size_t idx = (size_t)(n0 + i) * GK_ + k0 + tx;
        hi[idx] = h;
        lo[idx] = __float2bfloat16(v - __bfloat162float(h));
    }
}

// ---------------- shared GEMM mainloop (512 threads, 16 warps, warp tile 32x32) ----------------
#define TS_B        80
#define TILE_BYTES  (128 * TS_B)
#define STAGE_BYTES (4 * TILE_BYTES)
#define GEMM_SMEM   (3 * STAGE_BYTES)     // 122880

#define GEMM_BODY(Ahi, Alo, Bhi, Blo, m0, n0)                                  \
    extern __shared__ char sm[];                                               \
    const uint32_t sb = smem_u32(sm);                                          \
    const int tid = threadIdx.x, wid = tid >> 5, lane = tid & 31;              \
    const int g = lane >> 2, tig = lane & 3;                                   \
    const int wmb = (wid >> 2) * 32, wnb = (wid & 3) * 32;                     \
    const int arow = lane & 15, akof = (lane >> 4) << 4;                       \
    const int brow = (lane & 7) + ((lane >> 4) << 3), bkof = ((lane >> 3) & 1) << 4; \
    float acc[2][4][4];                                                        \
    _Pragma("unroll")                                                          \
    for (int a = 0; a < 2; a++)                                                \
        _Pragma("unroll")                                                      \
        for (int b = 0; b < 4; b++)                                            \
            _Pragma("unroll")                                                  \
            for (int c = 0; c < 4; c++) acc[a][b][c] = 0.f;                    \
    LOAD_STAGE(0, 0);                                                          \
    CPCOMMIT();                                                                \
    LOAD_STAGE(1, 32);                                                         \
    CPCOMMIT();                                                                \
    int stage = 0;                                                             \
    for (int kt = 0; kt < 32; kt++) {                                          \
        if (kt + 2 < 32) {                                                     \
            int ns = kt + 2 - ((kt + 2) / 3) * 3;                              \
            LOAD_STAGE(ns, (kt + 2) * 32);                                     \
            CPCOMMIT();                                                        \
            CPWAIT(2);                                                         \
        } else if (kt == 30) {                                                 \
            CPWAIT(1);                                                         \
        } else {                                                               \
            CPWAIT(0);                                                         \
        }                                                                      \
        __syncthreads();                                                       \
        const uint32_t baseA = sb + stage * STAGE_BYTES;                       \
        const uint32_t baseB = baseA + 2 * TILE_BYTES;                         \
        _Pragma("unroll")                                                      \
        for (int ks = 0; ks < 2; ks++) {                                       \
            uint32_t ah[2][4], al[2][4], bh2[2][4], bl2[2][4];                 \
            _Pragma("unroll")                                                  \
            for (int mt = 0; mt < 2; mt++) {                                   \
                uint32_t a0 = baseA + (wmb + mt * 16 + arow) * TS_B + ks * 32 + akof; \
                LDSM4(ah[mt], a0);                                             \
                LDSM4(al[mt], a0 + TILE_BYTES);                                \
            }                                                                  \
            _Pragma("unroll")                                                  \
            for (int np = 0; np < 2; np++) {                                   \
                uint32_t b0 = baseB + (wnb + np * 16 + brow) * TS_B + ks * 32 + bkof; \
                LDSM4(bh2[np], b0);                                            \
                LDSM4(bl2[np], b0 + TILE_BYTES);                               \
            }                                                                  \
            _Pragma("unroll")                                                  \
            for (int mt = 0; mt < 2; mt++)                                     \
                _Pragma("unroll")                                              \
                for (int nt = 0; nt < 4; nt++) {                               \
                    const uint32_t* bhp = &bh2[nt >> 1][(nt & 1) * 2];         \
                    const uint32_t* blp = &bl2[nt >> 1][(nt & 1) * 2];         \
                    mma16816(acc[mt][nt], ah[mt], bhp);                        \
                    mma16816(acc[mt][nt], ah[mt], blp);                        \
                    mma16816(acc[mt][nt], al[mt], bhp);                        \
                }                                                              \
        }                                                                      \
        __syncthreads();                                                       \
        stage = (stage == 2) ? 0 : stage + 1;                                  \
    }

#define LOAD_STAGE(stage, k0)                                                  \
    do {                                                                       \
        int r = tid >> 2, c = tid & 3;                                         \
        uint32_t so = sb + (stage) * STAGE_BYTES + r * TS_B + c * 16;          \
        size_t ga = (size_t)(m0 + r) * GK_ + (k0) + c * 8;                     \
        size_t gb = (size_t)(n0 + r) * GK_ + (k0) + c * 8;                     \
        CP16(so,                  Ahi + ga);                                   \
        CP16(so + TILE_BYTES,     Alo + ga);                                   \
        CP16(so + 2 * TILE_BYTES, Bhi + gb);                                   \
        CP16(so + 3 * TILE_BYTES, Blo + gb);                                   \
    } while (0)

// ---------------- fused QKV GEMM: [8192,1024] x [1024,3072] ----------------
__global__ __launch_bounds__(512, 1) void gemm_qkv_kernel(
    const __nv_bfloat16* __restrict__ Ahi, const __nv_bfloat16* __restrict__ Alo,
    const __nv_bfloat16* __restrict__ Bhi, const __nv_bfloat16* __restrict__ Blo,
    const float* __restrict__ bq, const float* __restrict__ bk, const float* __restrict__ bv,
    float* __restrict__ Cq, float* __restrict__ Ck, float* __restrict__ Cv) {
    const int m0 = blockIdx.y * 128, n0 = blockIdx.x * 128;   // n0 in [0,3072)
    GEMM_BODY(Ahi, Alo, Bhi, Blo, m0, n0)

    const int seg = blockIdx.x >> 3;                  // 0=Q 1=K 2=V
    const int nl0 = (blockIdx.x & 7) * 128;           // local col base
    const float* bias = (seg == 0) ? bq : (seg == 1) ? bk : bv;
    float* C = (seg == 0) ? Cq : (seg == 1) ? Ck : Cv;
#pragma unroll
    for (int mt = 0; mt < 2; mt++) {
        int r0 = m0 + wmb + mt * 16 + g;
#pragma unroll
        for (int nt = 0; nt < 4; nt++) {
            int cc = nl0 + wnb + nt * 8 + tig * 2;
            float b0 = bias[cc], b1 = bias[cc + 1];
            float2 v0, v1;
            v0.x = acc[mt][nt][0] + b0; v0.y = acc[mt][nt][1] + b1;
            v1.x = acc[mt][nt][2] + b0; v1.y = acc[mt][nt][3] + b1;
            *(float2*)(C + (size_t)r0 * GK_ + cc) = v0;
            *(float2*)(C + (size_t)(r0 + 8) * GK_ + cc) = v1;
        }
    }
}

// ---------------- output-projection GEMM (single output) ----------------
__global__ __launch_bounds__(512, 1) void gemm_mma_kernel(
    const __nv_bfloat16* __restrict__ Ahi, const __nv_bfloat16* __restrict__ Alo,
    const __nv_bfloat16* __restrict__ Bhi, const __nv_bfloat16* __restrict__ Blo,
    const float* __restrict__ bias, float* __restrict__ C) {
    const int m0 = blockIdx.y * 128, n0 = blockIdx.x * 128;
    GEMM_BODY(Ahi, Alo, Bhi, Blo, m0, n0)

#pragma unroll
    for (int mt = 0; mt < 2; mt++) {
        int r0 = m0 + wmb + mt * 16 + g;
#pragma unroll
        for (int nt = 0; nt < 4; nt++) {
            int cc = n0 + wnb + nt * 8 + tig * 2;
            float b0 = bias[cc], b1 = bias[cc + 1];
            float2 v0, v1;
            v0.x = acc[mt][nt][0] + b0; v0.y = acc[mt][nt][1] + b1;
            v1.x = acc[mt][nt][2] + b0; v1.y = acc[mt][nt][3] + b1;
            *(float2*)(C + (size_t)r0 * GK_ + cc) = v0;
            *(float2*)(C + (size_t)(r0 + 8) * GK_ + cc) = v1;
        }
    }
}
#undef LOAD_STAGE

// ---------------- RoPE + split + relayout to [b][h][t][64] ----------------
__global__ void rope_split_kernel(const float* __restrict__ q, const float* __restrict__ k,
                                  __nv_bfloat16* __restrict__ qh, __nv_bfloat16* __restrict__ ql,
                                  __nv_bfloat16* __restrict__ kh, __nv_bfloat16* __restrict__ kl) {
    int idx = blockIdx.x * blockDim.x + threadIdx.x;
    int p = idx & 31;
    int h = (idx >> 5) & (H_ - 1);
    int t = (idx >> 9) & (T_ - 1);
    int b = idx >> 20;
    double e = -((double)(2 * p) / 64.0) * 9.210340371976184;
    float inv = (float)exp(e);
    float ang = (float)t * inv;
    float sn, cs;
    sincosf(ang, &sn, &cs);
    size_t src = (((size_t)b * T_ + t) * H_ + h) * DH_ + 2 * p;
    size_t dst2 = ((((size_t)b * H_ + h) * T_ + t) * DH_ + 2 * p) >> 1;  // b32 index
    float x1 = q[src], x2 = q[src + 1];
    float r1 = x1 * cs - x2 * sn, r2 = x1 * sn + x2 * cs;
    uint32_t hp = pack_bf2(r1, r2);
    ((uint32_t*)qh)[dst2] = hp;
    ((uint32_t*)ql)[dst2] = pack_res(hp, r1, r2);
    x1 = k[src]; x2 = k[src + 1];
    r1 = x1 * cs - x2 * sn; r2 = x1 * sn + x2 * cs;
    hp = pack_bf2(r1, r2);
    ((uint32_t*)kh)[dst2] = hp;
    ((uint32_t*)kl)[dst2] = pack_res(hp, r1, r2);
}

// ---------------- V: split + transpose to [b][h][64][t] ----------------
__global__ void v_split_T_kernel(const float* __restrict__ v,
                                 __nv_bfloat16* __restrict__ vth,
                                 __nv_bfloat16* __restrict__ vtl) {
    __shared__ float tile[32][33];
    const int t0 = blockIdx.x * 32, d0 = blockIdx.y * 32;
    const int b = blockIdx.z >> 4, h = blockIdx.z & 15;
    const int tx = threadIdx.x, ty = threadIdx.y;       // (32, 8)
#pragma unroll
    for (int i = ty; i < 32; i += 8)
        tile[i][tx] = v[(((size_t)b * T_ + t0 + i) * H_ + h) * DH_ + d0 + tx];
    __syncthreads();
#pragma unroll
    for (int i = ty; i < 32; i += 8) {
        float val = tile[tx][i];                          // v[t0+tx][d0+i]
        __nv_bfloat16 hv = __float2bfloat16(val);
        size_t idx = (((size_t)b * H_ + h) * DH_ + d0 + i) * T_ + t0 + tx;
        vth[idx] = hv;
        vtl[idx] = __float2bfloat16(val - __bfloat162float(hv));
    }
}

// ---------------- mma.sync flash attention (ldmatrix, fused split output) ----------------
#define AT_STRIDE 144                       // bytes per 64-col bf16 row (72 b16)
#define AT_QH     0
#define AT_QL     18432
#define AT_STG0   36864
#define AT_TILE   9216                      // one 64x72 bf16 tile
#define AT_STGSZ  (4 * AT_TILE)             // kh,kl,vh,vl
#define ATT_SMEM  (AT_STG0 + 2 * AT_STGSZ)  // 110592

__global__ __launch_bounds__(256) void attn_mma_kernel(
    const __nv_bfloat16* __restrict__ Qh, const __nv_bfloat16* __restrict__ Ql,
    const __nv_bfloat16* __restrict__ Kh, const __nv_bfloat16* __restrict__ Kl,
    const __nv_bfloat16* __restrict__ Vth, const __nv_bfloat16* __restrict__ Vtl,
    const int* __restrict__ lens,
    __nv_bfloat16* __restrict__ Ohi, __nv_bfloat16* __restrict__ Olo) {
    extern __shared__ char sm[];
    const uint32_t sb = smem_u32(sm);
    const int tid = threadIdx.x, wid = tid >> 5, lane = tid & 31;
    const int g = lane >> 2, tig = lane & 3;
    const int q0 = blockIdx.x * 128, h = blockIdx.y, b = blockIdx.z;
    const int len = lens[b];
    const size_t hb = ((size_t)b * H_ + h) * T_;       // row base of [b][h][t][64]
    const size_t vb_g = ((size_t)b * H_ + h) * DH_;    // row base of [b][h][64][t]
    const int arow = lane & 15, akof = (lane >> 4) << 4;
    const int brow = (lane & 7) + ((lane >> 4) << 3), bkof = ((lane >> 3) & 1) << 4;

    // Q tile (128 rows, hi+lo)
#pragma unroll
    for (int i = 0; i < 4; i++) {
        int lin = tid + i * 256;
        int r = lin >> 3, c = lin & 7;
        uint32_t so = sb + AT_QH + r * AT_STRIDE + c * 16;
        size_t gi = (hb + q0 + r) * DH_ + c * 8;
        CP16(so, Qh + gi);
        CP16(so + AT_QL, Ql + gi);
    }

#define LOAD_KV(stg, kv0)                                                      \
    do {                                                                       \
        _Pragma("unroll")                                                      \
        for (int i = 0; i < 2; i++) {                                          \
            int lin = tid + i * 256;                                           \
            int r = lin >> 3, c = lin & 7;                                     \
            uint32_t so = sb + AT_STG0 + (stg) * AT_STGSZ + r * AT_STRIDE + c * 16; \
            size_t gk = (hb + (kv0) + r) * DH_ + c * 8;                        \
            size_t gv = (vb_g + r) * T_ + (kv0) + c * 8;                       \
            CP16(so,               Kh + gk);                                   \
            CP16(so + AT_TILE,     Kl + gk);                                   \
            CP16(so + 2 * AT_TILE, Vth + gv);                                  \
            CP16(so + 3 * AT_TILE, Vtl + gv);                                  \
        }                                                                      \
    } while (0)

    LOAD_KV(0, 0);
    CPCOMMIT();

    const int kend = min(q0 + 128, len);
    const int nt = (kend + 63) >> 6;

    float m0r = -INFINITY, m1r = -INFINITY, l0 = 0.f, l1 = 0.f;
    float o[8][4];
#pragma unroll
    for (int nb = 0; nb < 8; nb++)
#pragma unroll
        for (int c = 0; c < 4; c++) o[nb][c] = 0.f;
    uint32_t qfh[4][4], qfl[4][4];

    for (int t = 0; t < nt; t++) {
        if (t + 1 < nt) {
            LOAD_KV((t + 1) & 1, (t + 1) * 64);
            CPCOMMIT();
            CPWAIT(1);
        } else {
            CPWAIT(0);
        }
        __syncthreads();

        if (t == 0) {
#pragma unroll
            for (int ks = 0; ks < 4; ks++) {
                uint32_t a0 = sb + AT_QH + (wid * 16 + arow) * AT_STRIDE + ks * 32 + akof;
                LDSM4(qfh[ks], a0);
                LDSM4(qfl[ks], a0 + AT_QL);
            }
        }

        const uint32_t kbase = sb + AT_STG0 + (t & 1) * AT_STGSZ;
        // ---- S = Q K^T (3-term split) ----
        float s[8][4];
#pragma unroll
        for (int nb = 0; nb < 8; nb++)
#pragma unroll
            for (int c = 0; c < 4; c++) s[nb][c] = 0.f;
#pragma unroll
        for (int ks = 0; ks < 4; ks++) {
#pragma unroll
            for (int np = 0; np < 4; np++) {
                uint32_t ba = kbase + (np * 16 + brow) * AT_STRIDE + ks * 32 + bkof;
                uint32_t bh2[4], bl2[4];
                LDSM4(bh2, ba);
                LDSM4(bl2, ba + AT_TILE);
                mma16816(s[2 * np], qfh[ks], bh2);
                mma16816(s[2 * np], qfh[ks], bl2);
                mma16816(s[2 * np], qfl[ks], bh2);
                mma16816(s[2 * np + 1], qfh[ks], bh2 + 2);
                mma16816(s[2 * np + 1], qfh[ks], bl2 + 2);
                mma16816(s[2 * np + 1], qfl[ks], bh2 + 2);
            }
        }

        // ---- scale, cap, mask ----
        const int kv0 = t * 64;
        const int qr0 = q0 + wid * 16 + g, qr1 = qr0 + 8;
#pragma unroll
        for (int nb = 0; nb < 8; nb++) {
            int c0 = kv0 + nb * 8 + tig * 2, c1 = c0 + 1;
            float x;
            x = s[nb][0] * 0.125f; x = CAP_ * fast_tanh(x * (1.f / CAP_));
            s[nb][0] = (c0 > qr0 || c0 >= len) ? -INFINITY : x;
            x = s[nb][1] * 0.125f; x = CAP_ * fast_tanh(x * (1.f / CAP_));
            s[nb][1] = (c1 > qr0 || c1 >= len) ? -INFINITY : x;
            x = s[nb][2] * 0.125f; x = CAP_ * fast_tanh(x * (1.f / CAP_));
            s[nb][2] = (c0 > qr1 || c0 >= len) ? -INFINITY : x;
            x = s[nb][3] * 0.125f; x = CAP_ * fast_tanh(x * (1.f / CAP_));
            s[nb][3] = (c1 > qr1 || c1 >= len) ? -INFINITY : x;
        }

        // ---- online softmax ----
        float mt0 = -INFINITY, mt1 = -INFINITY;
#pragma unroll
        for (int nb = 0; nb < 8; nb++) {
            mt0 = fmaxf(mt0, fmaxf(s[nb][0], s[nb][1]));
            mt1 = fmaxf(mt1, fmaxf(s[nb][2], s[nb][3]));
        }
        mt0 = fmaxf(mt0, __shfl_xor_sync(0xffffffffu, mt0, 1));
        mt0 = fmaxf(mt0, __shfl_xor_sync(0xffffffffu, mt0, 2));
        mt1 = fmaxf(mt1, __shfl_xor_sync(0xffffffffu, mt1, 1));
        mt1 = fmaxf(mt1, __shfl_xor_sync(0xffffffffu, mt1, 2));
        float mn0 = fmaxf(m0r, mt0), mn1 = fmaxf(m1r, mt1);
        float al0 = __expf(m0r - mn0), al1 = __expf(m1r - mn1);

        uint32_t pah[4][4], pal[4][4];
        float rs0 = 0.f, rs1 = 0.f;
#pragma unroll
        for (int j = 0; j < 4; j++) {
#pragma unroll
            for (int half = 0; half < 2; half++) {
                int blk = 2 * j + half;
                float p0 = __expf(s[blk][0] - mn0);
                float p1 = __expf(s[blk][1] - mn0);
                float p2 = __expf(s[blk][2] - mn1);
                float p3 = __expf(s[blk][3] - mn1);
                rs0 += p0 + p1; rs1 += p2 + p3;
                uint32_t u01 = pack_bf2(p0, p1);
                uint32_t u23 = pack_bf2(p2, p3);
                pah[j][half * 2]     = u01;
                pah[j][half * 2 + 1] = u23;
                pal[j][half * 2]     = pack_res(u01, p0, p1);
                pal[j][half * 2 + 1] = pack_res(u23, p2, p3);
            }
        }
        rs0 += __shfl_xor_sync(0xffffffffu, rs0, 1);
        rs0 += __shfl_xor_sync(0xffffffffu, rs0, 2);
        rs1 += __shfl_xor_sync(0xffffffffu, rs1, 1);
        rs1 += __shfl_xor_sync(0xffffffffu, rs1, 2);
        l0 = l0 * al0 + rs0; m0r = mn0;
        l1 = l1 * al1 + rs1; m1r = mn1;
#pragma unroll
        for (int nb = 0; nb < 8; nb++) {
            o[nb][0] *= al0; o[nb][1] *= al0;
            o[nb][2] *= al1; o[nb][3] *= al1;
        }

        // ---- O += P V (3-term split), V transposed in smem ----
        const uint32_t vbase = kbase + 2 * AT_TILE;
#pragma unroll
        for (int j = 0; j < 4; j++) {
#pragma unroll
            for (int np = 0; np < 4; np++) {
                uint32_t ba = vbase + (np * 16 + brow) * AT_STRIDE + j * 32 + bkof;
                uint32_t bh2[4], bl2[4];
                LDSM4(bh2, ba);
                LDSM4(bl2, ba + AT_TILE);
                mma16816(o[2 * np], pah[j], bh2);
                mma16816(o[2 * np], pah[j], bl2);
                mma16816(o[2 * np], pal[j], bh2);
                mma16816(o[2 * np + 1], pah[j], bh2 + 2);
                mma16816(o[2 * np + 1], pah[j], bl2 + 2);
                mma16816(o[2 * np + 1], pal[j], bh2 + 2);
            }
        }
        __syncthreads();
    }

    // ---- fused epilogue: normalize + hi/lo split to [b][t][h*64] bf16 ----
    float i0 = (l0 > 0.f) ? (1.f / l0) : 0.f;
    float i1 = (l1 > 0.f) ? (1.f / l1) : 0.f;
    const int qr0 = q0 + wid * 16 + g, qr1 = qr0 + 8;
#pragma unroll
    for (int nb = 0; nb < 8; nb++) {
        int cc = h * DH_ + nb * 8 + tig * 2;
        float p0 = o[nb][0] * i0, p1 = o[nb][1] * i0;
        float p2 = o[nb][2] * i1, p3 = o[nb][3] * i1;
        uint32_t u0 = pack_bf2(p0, p1), u1 = pack_bf2(p2, p3);
        size_t i0x = (((size_t)b * T_ + qr0) * D_ + cc) >> 1;
        size_t i1x = (((size_t)b * T_ + qr1) * D_ + cc) >> 1;
        ((uint32_t*)Ohi)[i0x] = u0;
        ((uint32_t*)Olo)[i0x] = pack_res(u0, p0, p1);
        ((uint32_t*)Ohi)[i1x] = u1;
        ((uint32_t*)Olo)[i1x] = pack_res(u1, p2, p3);
    }
#undef LOAD_KV
}

// ---------------- launcher ----------------
extern "C" void kernel_launch(void* const* d_in, const int* in_sizes, int n_in,
                              void* d_out, int out_size) {
    const float* x    = (const float*)d_in[0];
    const float* ln_g = (const float*)d_in[1];
    const float* ln_b = (const float*)d_in[2];
    const float* Wq   = (const float*)d_in[3];
    const float* bq   = (const float*)d_in[4];
    const float* Wk   = (const float*)d_in[5];
    const float* bk   = (const float*)d_in[6];
    const float* Wv   = (const float*)d_in[7];
    const float* bv   = (const float*)d_in[8];
    const float* Wo   = (const float*)d_in[9];
    const float* bo   = (const float*)d_in[10];
    const int*  lens  = (const int*)d_in[13];
    float* out = (float*)d_out;

    float *q_, *k_, *v_;
    __nv_bfloat16 *ahi, *alo, *whi, *wlo, *qh, *ql, *kh, *kl, *vth, *vtl;
    cudaGetSymbolAddress((void**)&q_, g_q);
    cudaGetSymbolAddress((void**)&k_, g_k);
    cudaGetSymbolAddress((void**)&v_, g_v);
    cudaGetSymbolAddress((void**)&ahi, g_ahi);
    cudaGetSymbolAddress((void**)&alo, g_alo);
    cudaGetSymbolAddress((void**)&whi, g_whi);
    cudaGetSymbolAddress((void**)&wlo, g_wlo);
    cudaGetSymbolAddress((void**)&qh, g_qh);
    cudaGetSymbolAddress((void**)&ql, g_ql);
    cudaGetSymbolAddress((void**)&kh, g_kh);
    cudaGetSymbolAddress((void**)&kl, g_kl);
    cudaGetSymbolAddress((void**)&vth, g_vth);
    cudaGetSymbolAddress((void**)&vtl, g_vtl);

    cudaFuncSetAttribute(gemm_qkv_kernel, cudaFuncAttributeMaxDynamicSharedMemorySize, GEMM_SMEM);
    cudaFuncSetAttribute(gemm_mma_kernel, cudaFuncAttributeMaxDynamicSharedMemorySize, GEMM_SMEM);
    cudaFuncSetAttribute(attn_mma_kernel, cudaFuncAttributeMaxDynamicSharedMemorySize, ATT_SMEM);

    // LN fused with split
    ln_split_kernel<<<ROWS_, 256>>>(x, ln_g, ln_b, ahi, alo);

    // W^T segments: Q->rows[0,1024), K->rows[1024,2048), V->rows[2048,3072)
    const dim3 tg(32, 32), tb(32, 8);
    transpose_split_kernel<<<tg, tb>>>(Wq, whi, wlo);
    transpose_split_kernel<<<tg, tb>>>(Wk, whi + (size_t)GK_ * GK_, wlo + (size_t)GK_ * GK_);
    transpose_split_kernel<<<tg, tb>>>(Wv, whi + (size_t)2 * GK_ * GK_, wlo + (size_t)2 * GK_ * GK_);

    // fused QKV projection (512 threads, 16 warps)
    gemm_qkv_kernel<<<dim3(24, 64), 512, GEMM_SMEM>>>(ahi, alo, whi, wlo,
                                                      bq, bk, bv, q_, k_, v_);

    rope_split_kernel<<<(N_ * T_ * H_ * 32) / 256, 256>>>(q_, k_, qh, ql, kh, kl);
    v_split_T_kernel<<<dim3(T_ / 32, DH_ / 32, N_ * H_), dim3(32, 8)>>>(v_, vth, vtl);

    // attention writes hi/lo split output directly
    attn_mma_kernel<<<dim3(T_ / 128, H_, N_), 256, ATT_SMEM>>>(qh, ql, kh, kl, vth, vtl, lens, ahi, alo);

    // Wo^T into segment 0 (QKV GEMM already consumed it; stream order protects)
    transpose_split_kernel<<<tg, tb>>>(Wo, whi, wlo);
    gemm_mma_kernel<<<dim3(8, 64), 512, GEMM_SMEM>>>(ahi, alo, whi, wlo, bo, out);
}

// round 17
// speedup vs baseline: 1.0299x; 1.0299x over previous
#include <cuda_runtime.h>
#include <cuda_bf16.h>
#include <math.h>
#include <stdint.h>

#define N_   4
#define T_   2048
#define D_   1024
#define H_   16
#define DH_  64
#define CAP_ 30.0f
#define EPS_ 1e-5f
#define ROWS_ (N_ * T_)          // 8192
#define GK_  1024

// ---------------- scratch (device globals: allocation-free) ----------------
__device__ float g_q[(size_t)ROWS_ * H_ * DH_];
__device__ float g_k[(size_t)ROWS_ * H_ * DH_];
__device__ float g_v[(size_t)ROWS_ * H_ * DH_];
__device__ __nv_bfloat16 g_ahi[(size_t)ROWS_ * GK_];
__device__ __nv_bfloat16 g_alo[(size_t)ROWS_ * GK_];
__device__ __nv_bfloat16 g_whi[(size_t)3 * GK_ * GK_];   // W^T hi: QKV segments [3072,1024]
__device__ __nv_bfloat16 g_wlo[(size_t)3 * GK_ * GK_];
// attention operands, head-major
__device__ __nv_bfloat16 g_qh[(size_t)ROWS_ * GK_];  // [b][h][t][64]
__device__ __nv_bfloat16 g_ql[(size_t)ROWS_ * GK_];
__device__ __nv_bfloat16 g_kh[(size_t)ROWS_ * GK_];
__device__ __nv_bfloat16 g_kl[(size_t)ROWS_ * GK_];
__device__ __nv_bfloat16 g_vth[(size_t)ROWS_ * GK_]; // [b][h][64][t]  (V transposed)
__device__ __nv_bfloat16 g_vtl[(size_t)ROWS_ * GK_];

// ---------------- helpers ----------------
__device__ __forceinline__ uint32_t smem_u32(const void* p) {
    uint32_t a;
    asm("{ .reg .u64 t; cvta.to.shared.u64 t, %1; cvt.u32.u64 %0, t; }" : "=r"(a) : "l"(p));
    return a;
}
__device__ __forceinline__ float fast_tanh(float x) {
    asm("tanh.approx.f32 %0, %0;" : "+f"(x));
    return x;
}
#define LDSM4(r, a)                                                           \
    asm volatile("ldmatrix.sync.aligned.m8n8.x4.shared.b16 {%0,%1,%2,%3}, [%4];" \
                 : "=r"((r)[0]), "=r"((r)[1]), "=r"((r)[2]), "=r"((r)[3]) : "r"(a))
#define CP16(sa, gp) asm volatile("cp.async.cg.shared.global [%0], [%1], 16;" :: "r"(sa), "l"(gp))
#define CPCOMMIT() asm volatile("cp.async.commit_group;" ::: "memory")
#define CPWAIT(n)  asm volatile("cp.async.wait_group %0;" :: "n"(n) : "memory")

__device__ __forceinline__ void mma16816(float* c, const uint32_t* a, const uint32_t* b) {
    asm volatile(
        "mma.sync.aligned.m16n8k16.row.col.f32.bf16.bf16.f32 "
        "{%0,%1,%2,%3}, {%4,%5,%6,%7}, {%8,%9}, {%0,%1,%2,%3};"
        : "+f"(c[0]), "+f"(c[1]), "+f"(c[2]), "+f"(c[3])
        : "r"(a[0]), "r"(a[1]), "r"(a[2]), "r"(a[3]), "r"(b[0]), "r"(b[1]));
}
__device__ __forceinline__ uint32_t pack_bf2(float p0, float p1) {
    uint32_t r;
    asm("cvt.rn.bf16x2.f32 %0, %1, %2;" : "=r"(r) : "f"(p1), "f"(p0));
    return r;
}
__device__ __forceinline__ uint32_t pack_res(uint32_t hi, float p0, float p1) {
    float h0 = __uint_as_float(hi << 16);
    float h1 = __uint_as_float(hi & 0xFFFF0000u);
    return pack_bf2(p0 - h0, p1 - h1);
}

// ---------------- LayerNorm fused with hi/lo split ----------------
__global__ void ln_split_kernel(const float* __restrict__ x, const float* __restrict__ gw,
                                const float* __restrict__ bw,
                                __nv_bfloat16* __restrict__ hi, __nv_bfloat16* __restrict__ lo) {
    __shared__ float red[8];
    __shared__ float stat[2];
    const int row = blockIdx.x;
    const int t = threadIdx.x;            // 256 threads, 4 consecutive cols each
    const float4 v = ((const float4*)(x + (size_t)row * D_))[t];
    float s = v.x + v.y + v.z + v.w;
#pragma unroll
    for (int o = 16; o; o >>= 1) s += __shfl_xor_sync(0xffffffffu, s, o);
    if ((t & 31) == 0) red[t >> 5] = s;
    __syncthreads();
    if (t == 0) {
        float tot = 0.f;
#pragma unroll
        for (int i = 0; i < 8; i++) tot += red[i];
        stat[0] = tot * (1.f / D_);
    }
    __syncthreads();
    const float mean = stat[0];
    float d0 = v.x - mean, d1 = v.y - mean, d2 = v.z - mean, d3 = v.w - mean;
    float ss = d0 * d0 + d1 * d1 + d2 * d2 + d3 * d3;
#pragma unroll
    for (int o = 16; o; o >>= 1) ss += __shfl_xor_sync(0xffffffffu, ss, o);
    if ((t & 31) == 0) red[t >> 5] = ss;
    __syncthreads();
    if (t == 0) {
        float tot = 0.f;
#pragma unroll
        for (int i = 0; i < 8; i++) tot += red[i];
        stat[1] = rsqrtf(tot * (1.f / D_) + EPS_);
    }
    __syncthreads();
    const float rs = stat[1];
    const float4 gv = ((const float4*)gw)[t];
    const float4 bv = ((const float4*)bw)[t];
    float y0 = d0 * rs * gv.x + bv.x;
    float y1 = d1 * rs * gv.y + bv.y;
    float y2 = d2 * rs * gv.z + bv.z;
    float y3 = d3 * rs * gv.w + bv.w;
    uint32_t h0 = pack_bf2(y0, y1), h1 = pack_bf2(y2, y3);
    size_t bidx = ((size_t)row * D_ + t * 4) >> 1;
    ((uint32_t*)hi)[bidx] = h0;
    ((uint32_t*)hi)[bidx + 1] = h1;
    ((uint32_t*)lo)[bidx] = pack_res(h0, y0, y1);
    ((uint32_t*)lo)[bidx + 1] = pack_res(h1, y2, y3);
}

// ---------------- transpose + split: W[K,N] fp32 -> W^T hi/lo bf16 [N,K] ----------------
__global__ void transpose_split_kernel(const float* __restrict__ W,
                                       __nv_bfloat16* __restrict__ hi,
                                       __nv_bfloat16* __restrict__ lo) {
    __shared__ float tile[32][33];
    const int k0 = blockIdx.y * 32, n0 = blockIdx.x * 32;
    const int tx = threadIdx.x, ty = threadIdx.y;        // (32, 8)
#pragma unroll
    for (int i = ty; i < 32; i += 8)
        tile[i][tx] = W[(size_t)(k0 + i) * GK_ + n0 + tx];
    __syncthreads();
#pragma unroll
    for (int i = ty; i < 32; i += 8) {
        float v = tile[tx][i];
        __nv_bfloat16 h = __float2bfloat16(v);
        size_t idx = (size_t)(n0 + i) * GK_ + k0 + tx;
        hi[idx] = h;
        lo[idx] = __float2bfloat16(v - __bfloat162float(h));
    }
}

// ---------------- GEMM mainloop: 128x256 CTA tile, 256 threads, warp tile 64x64 ----------------
#define TS_B        80
#define GA_BYTES    (128 * TS_B)          // 10240  (A tile, 128 rows)
#define GB_BYTES    (256 * TS_B)          // 20480  (B tile, 256 rows)
#define STAGE_BYTES (2 * GA_BYTES + 2 * GB_BYTES)   // 61440
#define GEMM_SMEM   (3 * STAGE_BYTES)     // 184320

#define GEMM_BODY(Ahi, Alo, Bhi, Blo, m0, n0)                                  \
    extern __shared__ char sm[];                                               \
    const uint32_t sb = smem_u32(sm);                                          \
    const int tid = threadIdx.x, wid = tid >> 5, lane = tid & 31;              \
    const int g = lane >> 2, tig = lane & 3;                                   \
    const int wmb = (wid >> 2) * 64, wnb = (wid & 3) * 64;                     \
    const int arow = lane & 15, akof = (lane >> 4) << 4;                       \
    const int brow = (lane & 7) + ((lane >> 4) << 3), bkof = ((lane >> 3) & 1) << 4; \
    float acc[4][8][4];                                                        \
    _Pragma("unroll")                                                          \
    for (int a = 0; a < 4; a++)                                                \
        _Pragma("unroll")                                                      \
        for (int b = 0; b < 8; b++)                                            \
            _Pragma("unroll")                                                  \
            for (int c = 0; c < 4; c++) acc[a][b][c] = 0.f;                    \
    LOAD_STAGE(0, 0);                                                          \
    CPCOMMIT();                                                                \
    LOAD_STAGE(1, 32);                                                         \
    CPCOMMIT();                                                                \
    int stage = 0;                                                             \
    for (int kt = 0; kt < 32; kt++) {                                          \
        if (kt + 2 < 32) {                                                     \
            int ns = kt + 2 - ((kt + 2) / 3) * 3;                              \
            LOAD_STAGE(ns, (kt + 2) * 32);                                     \
            CPCOMMIT();                                                        \
            CPWAIT(2);                                                         \
        } else if (kt == 30) {                                                 \
            CPWAIT(1);                                                         \
        } else {                                                               \
            CPWAIT(0);                                                         \
        }                                                                      \
        __syncthreads();                                                       \
        const uint32_t baseA = sb + stage * STAGE_BYTES;                       \
        const uint32_t baseB = baseA + 2 * GA_BYTES;                           \
        _Pragma("unroll")                                                      \
        for (int ks = 0; ks < 2; ks++) {                                       \
            uint32_t ah[4][4], al[4][4], bh2[4][4], bl2[4][4];                 \
            _Pragma("unroll")                                                  \
            for (int mt = 0; mt < 4; mt++) {                                   \
                uint32_t a0 = baseA + (wmb + mt * 16 + arow) * TS_B + ks * 32 + akof; \
                LDSM4(ah[mt], a0);                                             \
                LDSM4(al[mt], a0 + GA_BYTES);                                  \
            }                                                                  \
            _Pragma("unroll")                                                  \
            for (int np = 0; np < 4; np++) {                                   \
                uint32_t b0 = baseB + (wnb + np * 16 + brow) * TS_B + ks * 32 + bkof; \
                LDSM4(bh2[np], b0);                                            \
                LDSM4(bl2[np], b0 + GB_BYTES);                                 \
            }                                                                  \
            _Pragma("unroll")                                                  \
            for (int mt = 0; mt < 4; mt++)                                     \
                _Pragma("unroll")                                              \
                for (int nt = 0; nt < 8; nt++) {                               \
                    const uint32_t* bhp = &bh2[nt >> 1][(nt & 1) * 2];         \
                    const uint32_t* blp = &bl2[nt >> 1][(nt & 1) * 2];         \
                    mma16816(acc[mt][nt], ah[mt], bhp);                        \
                    mma16816(acc[mt][nt], ah[mt], blp);                        \
                    mma16816(acc[mt][nt], al[mt], bhp);                        \
                }                                                              \
        }                                                                      \
        __syncthreads();                                                       \
        stage = (stage == 2) ? 0 : stage + 1;                                  \
    }

#define LOAD_STAGE(stage, k0)                                                  \
    do {                                                                       \
        _Pragma("unroll")                                                      \
        for (int i = 0; i < 2; i++) {                                          \
            int lin = tid + i * 256;                                           \
            int r = lin >> 2, c = lin & 3;                                     \
            uint32_t so = sb + (stage) * STAGE_BYTES + r * TS_B + c * 16;      \
            size_t ga = (size_t)(m0 + r) * GK_ + (k0) + c * 8;                 \
            CP16(so,            Ahi + ga);                                     \
            CP16(so + GA_BYTES, Alo + ga);                                     \
        }                                                                      \
        _Pragma("unroll")                                                      \
        for (int i = 0; i < 4; i++) {                                          \
            int lin = tid + i * 256;                                           \
            int r = lin >> 2, c = lin & 3;                                     \
            uint32_t so = sb + (stage) * STAGE_BYTES + 2 * GA_BYTES + r * TS_B + c * 16; \
            size_t gb = (size_t)(n0 + r) * GK_ + (k0) + c * 8;                 \
            CP16(so,            Bhi + gb);                                     \
            CP16(so + GB_BYTES, Blo + gb);                                     \
        }                                                                      \
    } while (0)

// ---------------- fused QKV GEMM: [8192,1024] x [1024,3072] ----------------
__global__ __launch_bounds__(256, 1) void gemm_qkv_kernel(
    const __nv_bfloat16* __restrict__ Ahi, const __nv_bfloat16* __restrict__ Alo,
    const __nv_bfloat16* __restrict__ Bhi, const __nv_bfloat16* __restrict__ Blo,
    const float* __restrict__ bq, const float* __restrict__ bk, const float* __restrict__ bv,
    float* __restrict__ Cq, float* __restrict__ Ck, float* __restrict__ Cv) {
    const int m0 = blockIdx.y * 128, n0 = blockIdx.x * 256;   // n0 in [0,3072)
    GEMM_BODY(Ahi, Alo, Bhi, Blo, m0, n0)

    const int seg = blockIdx.x >> 2;                  // 0=Q 1=K 2=V  (256-col tiles, 4 per segment)
    const int nl0 = (blockIdx.x & 3) * 256;           // local col base
    const float* bias = (seg == 0) ? bq : (seg == 1) ? bk : bv;
    float* C = (seg == 0) ? Cq : (seg == 1) ? Ck : Cv;
#pragma unroll
    for (int mt = 0; mt < 4; mt++) {
        int r0 = m0 + wmb + mt * 16 + g;
#pragma unroll
        for (int nt = 0; nt < 8; nt++) {
            int cc = nl0 + wnb + nt * 8 + tig * 2;
            float b0 = bias[cc], b1 = bias[cc + 1];
            float2 v0, v1;
            v0.x = acc[mt][nt][0] + b0; v0.y = acc[mt][nt][1] + b1;
            v1.x = acc[mt][nt][2] + b0; v1.y = acc[mt][nt][3] + b1;
            *(float2*)(C + (size_t)r0 * GK_ + cc) = v0;
            *(float2*)(C + (size_t)(r0 + 8) * GK_ + cc) = v1;
        }
    }
}

// ---------------- output-projection GEMM (single output) ----------------
__global__ __launch_bounds__(256, 1) void gemm_mma_kernel(
    const __nv_bfloat16* __restrict__ Ahi, const __nv_bfloat16* __restrict__ Alo,
    const __nv_bfloat16* __restrict__ Bhi, const __nv_bfloat16* __restrict__ Blo,
    const float* __restrict__ bias, float* __restrict__ C) {
    const int m0 = blockIdx.y * 128, n0 = blockIdx.x * 256;
    GEMM_BODY(Ahi, Alo, Bhi, Blo, m0, n0)

#pragma unroll
    for (int mt = 0; mt < 4; mt++) {
        int r0 = m0 + wmb + mt * 16 + g;
#pragma unroll
        for (int nt = 0; nt < 8; nt++) {
            int cc = n0 + wnb + nt * 8 + tig * 2;
            float b0 = bias[cc], b1 = bias[cc + 1];
            float2 v0, v1;
            v0.x = acc[mt][nt][0] + b0; v0.y = acc[mt][nt][1] + b1;
            v1.x = acc[mt][nt][2] + b0; v1.y = acc[mt][nt][3] + b1;
            *(float2*)(C + (size_t)r0 * GK_ + cc) = v0;
            *(float2*)(C + (size_t)(r0 + 8) * GK_ + cc) = v1;
        }
    }
}
#undef LOAD_STAGE

// ---------------- RoPE + split + relayout to [b][h][t][64] ----------------
__global__ void rope_split_kernel(const float* __restrict__ q, const float* __restrict__ k,
                                  __nv_bfloat16* __restrict__ qh, __nv_bfloat16* __restrict__ ql,
                                  __nv_bfloat16* __restrict__ kh, __nv_bfloat16* __restrict__ kl) {
    int idx = blockIdx.x * blockDim.x + threadIdx.x;
    int p = idx & 31;
    int h = (idx >> 5) & (H_ - 1);
    int t = (idx >> 9) & (T_ - 1);
    int b = idx >> 20;
    double e = -((double)(2 * p) / 64.0) * 9.210340371976184;
    float inv = (float)exp(e);
    float ang = (float)t * inv;
    float sn, cs;
    sincosf(ang, &sn, &cs);
    size_t src = (((size_t)b * T_ + t) * H_ + h) * DH_ + 2 * p;
    size_t dst2 = ((((size_t)b * H_ + h) * T_ + t) * DH_ + 2 * p) >> 1;  // b32 index
    float x1 = q[src], x2 = q[src + 1];
    float r1 = x1 * cs - x2 * sn, r2 = x1 * sn + x2 * cs;
    uint32_t hp = pack_bf2(r1, r2);
    ((uint32_t*)qh)[dst2] = hp;
    ((uint32_t*)ql)[dst2] = pack_res(hp, r1, r2);
    x1 = k[src]; x2 = k[src + 1];
    r1 = x1 * cs - x2 * sn; r2 = x1 * sn + x2 * cs;
    hp = pack_bf2(r1, r2);
    ((uint32_t*)kh)[dst2] = hp;
    ((uint32_t*)kl)[dst2] = pack_res(hp, r1, r2);
}

// ---------------- V: split + transpose to [b][h][64][t] ----------------
__global__ void v_split_T_kernel(const float* __restrict__ v,
                                 __nv_bfloat16* __restrict__ vth,
                                 __nv_bfloat16* __restrict__ vtl) {
    __shared__ float tile[32][33];
    const int t0 = blockIdx.x * 32, d0 = blockIdx.y * 32;
    const int b = blockIdx.z >> 4, h = blockIdx.z & 15;
    const int tx = threadIdx.x, ty = threadIdx.y;       // (32, 8)
#pragma unroll
    for (int i = ty; i < 32; i += 8)
        tile[i][tx] = v[(((size_t)b * T_ + t0 + i) * H_ + h) * DH_ + d0 + tx];
    __syncthreads();
#pragma unroll
    for (int i = ty; i < 32; i += 8) {
        float val = tile[tx][i];                          // v[t0+tx][d0+i]
        __nv_bfloat16 hv = __float2bfloat16(val);
        size_t idx = (((size_t)b * H_ + h) * DH_ + d0 + i) * T_ + t0 + tx;
        vth[idx] = hv;
        vtl[idx] = __float2bfloat16(val - __bfloat162float(hv));
    }
}

// ---------------- mma.sync flash attention (ldmatrix, fused split output) ----------------
#define AT_STRIDE 144                       // bytes per 64-col bf16 row (72 b16)
#define AT_QH     0
#define AT_QL     18432
#define AT_STG0   36864
#define AT_TILE   9216                      // one 64x72 bf16 tile
#define AT_STGSZ  (4 * AT_TILE)             // kh,kl,vh,vl
#define ATT_SMEM  (AT_STG0 + 2 * AT_STGSZ)  // 110592

__global__ __launch_bounds__(256) void attn_mma_kernel(
    const __nv_bfloat16* __restrict__ Qh, const __nv_bfloat16* __restrict__ Ql,
    const __nv_bfloat16* __restrict__ Kh, const __nv_bfloat16* __restrict__ Kl,
    const __nv_bfloat16* __restrict__ Vth, const __nv_bfloat16* __restrict__ Vtl,
    const int* __restrict__ lens,
    __nv_bfloat16* __restrict__ Ohi, __nv_bfloat16* __restrict__ Olo) {
    extern __shared__ char sm[];
    const uint32_t sb = smem_u32(sm);
    const int tid = threadIdx.x, wid = tid >> 5, lane = tid & 31;
    const int g = lane >> 2, tig = lane & 3;
    // reversed q-tile order: longest-running CTAs are scheduled first
    const int q0 = (gridDim.x - 1 - blockIdx.x) * 128;
    const int h = blockIdx.y, b = blockIdx.z;
    const int len = lens[b];
    const size_t hb = ((size_t)b * H_ + h) * T_;       // row base of [b][h][t][64]
    const size_t vb_g = ((size_t)b * H_ + h) * DH_;    // row base of [b][h][64][t]
    const int arow = lane & 15, akof = (lane >> 4) << 4;
    const int brow = (lane & 7) + ((lane >> 4) << 3), bkof = ((lane >> 3) & 1) << 4;

    // Q tile (128 rows, hi+lo)
#pragma unroll
    for (int i = 0; i < 4; i++) {
        int lin = tid + i * 256;
        int r = lin >> 3, c = lin & 7;
        uint32_t so = sb + AT_QH + r * AT_STRIDE + c * 16;
        size_t gi = (hb + q0 + r) * DH_ + c * 8;
        CP16(so, Qh + gi);
        CP16(so + AT_QL, Ql + gi);
    }

#define LOAD_KV(stg, kv0)                                                      \
    do {                                                                       \
        _Pragma("unroll")                                                      \
        for (int i = 0; i < 2; i++) {                                          \
            int lin = tid + i * 256;                                           \
            int r = lin >> 3, c = lin & 7;                                     \
            uint32_t so = sb + AT_STG0 + (stg) * AT_STGSZ + r * AT_STRIDE + c * 16; \
            size_t gk = (hb + (kv0) + r) * DH_ + c * 8;                        \
            size_t gv = (vb_g + r) * T_ + (kv0) + c * 8;                       \
            CP16(so,               Kh + gk);                                   \
            CP16(so + AT_TILE,     Kl + gk);                                   \
            CP16(so + 2 * AT_TILE, Vth + gv);                                  \
            CP16(so + 3 * AT_TILE, Vtl + gv);                                  \
        }                                                                      \
    } while (0)

    LOAD_KV(0, 0);
    CPCOMMIT();

    const int kend = min(q0 + 128, len);
    const int nt = (kend + 63) >> 6;

    float m0r = -INFINITY, m1r = -INFINITY, l0 = 0.f, l1 = 0.f;
    float o[8][4];
#pragma unroll
    for (int nb = 0; nb < 8; nb++)
#pragma unroll
        for (int c = 0; c < 4; c++) o[nb][c] = 0.f;
    uint32_t qfh[4][4], qfl[4][4];

    for (int t = 0; t < nt; t++) {
        if (t + 1 < nt) {
            LOAD_KV((t + 1) & 1, (t + 1) * 64);
            CPCOMMIT();
            CPWAIT(1);
        } else {
            CPWAIT(0);
        }
        __syncthreads();

        if (t == 0) {
#pragma unroll
            for (int ks = 0; ks < 4; ks++) {
                uint32_t a0 = sb + AT_QH + (wid * 16 + arow) * AT_STRIDE + ks * 32 + akof;
                LDSM4(qfh[ks], a0);
                LDSM4(qfl[ks], a0 + AT_QL);
            }
        }

        const uint32_t kbase = sb + AT_STG0 + (t & 1) * AT_STGSZ;
        // ---- S = Q K^T (3-term split) ----
        float s[8][4];
#pragma unroll
        for (int nb = 0; nb < 8; nb++)
#pragma unroll
            for (int c = 0; c < 4; c++) s[nb][c] = 0.f;
#pragma unroll
        for (int ks = 0; ks < 4; ks++) {
#pragma unroll
            for (int np = 0; np < 4; np++) {
                uint32_t ba = kbase + (np * 16 + brow) * AT_STRIDE + ks * 32 + bkof;
                uint32_t bh2[4], bl2[4];
                LDSM4(bh2, ba);
                LDSM4(bl2, ba + AT_TILE);
                mma16816(s[2 * np], qfh[ks], bh2);
                mma16816(s[2 * np], qfh[ks], bl2);
                mma16816(s[2 * np], qfl[ks], bh2);
                mma16816(s[2 * np + 1], qfh[ks], bh2 + 2);
                mma16816(s[2 * np + 1], qfh[ks], bl2 + 2);
                mma16816(s[2 * np + 1], qfl[ks], bh2 + 2);
            }
        }

        // ---- scale, cap, mask ----
        const int kv0 = t * 64;
        const int qr0 = q0 + wid * 16 + g, qr1 = qr0 + 8;
#pragma unroll
        for (int nb = 0; nb < 8; nb++) {
            int c0 = kv0 + nb * 8 + tig * 2, c1 = c0 + 1;
            float x;
            x = s[nb][0] * 0.125f; x = CAP_ * fast_tanh(x * (1.f / CAP_));
            s[nb][0] = (c0 > qr0 || c0 >= len) ? -INFINITY : x;
            x = s[nb][1] * 0.125f; x = CAP_ * fast_tanh(x * (1.f / CAP_));
            s[nb][1] = (c1 > qr0 || c1 >= len) ? -INFINITY : x;
            x = s[nb][2] * 0.125f; x = CAP_ * fast_tanh(x * (1.f / CAP_));
            s[nb][2] = (c0 > qr1 || c0 >= len) ? -INFINITY : x;
            x = s[nb][3] * 0.125f; x = CAP_ * fast_tanh(x * (1.f / CAP_));
            s[nb][3] = (c1 > qr1 || c1 >= len) ? -INFINITY : x;
        }

        // ---- online softmax ----
        float mt0 = -INFINITY, mt1 = -INFINITY;
#pragma unroll
        for (int nb = 0; nb < 8; nb++) {
            mt0 = fmaxf(mt0, fmaxf(s[nb][0], s[nb][1]));
            mt1 = fmaxf(mt1, fmaxf(s[nb][2], s[nb][3]));
        }
        mt0 = fmaxf(mt0, __shfl_xor_sync(0xffffffffu, mt0, 1));
        mt0 = fmaxf(mt0, __shfl_xor_sync(0xffffffffu, mt0, 2));
        mt1 = fmaxf(mt1, __shfl_xor_sync(0xffffffffu, mt1, 1));
        mt1 = fmaxf(mt1, __shfl_xor_sync(0xffffffffu, mt1, 2));
        float mn0 = fmaxf(m0r, mt0), mn1 = fmaxf(m1r, mt1);
        float al0 = __expf(m0r - mn0), al1 = __expf(m1r - mn1);

        uint32_t pah[4][4], pal[4][4];
        float rs0 = 0.f, rs1 = 0.f;
#pragma unroll
        for (int j = 0; j < 4; j++) {
#pragma unroll
            for (int half = 0; half < 2; half++) {
                int blk = 2 * j + half;
                float p0 = __expf(s[blk][0] - mn0);
                float p1 = __expf(s[blk][1] - mn0);
                float p2 = __expf(s[blk][2] - mn1);
                float p3 = __expf(s[blk][3] - mn1);
                rs0 += p0 + p1; rs1 += p2 + p3;
                uint32_t u01 = pack_bf2(p0, p1);
                uint32_t u23 = pack_bf2(p2, p3);
                pah[j][half * 2]     = u01;
                pah[j][half * 2 + 1] = u23;
                pal[j][half * 2]     = pack_res(u01, p0, p1);
                pal[j][half * 2 + 1] = pack_res(u23, p2, p3);
            }
        }
        rs0 += __shfl_xor_sync(0xffffffffu, rs0, 1);
        rs0 += __shfl_xor_sync(0xffffffffu, rs0, 2);
        rs1 += __shfl_xor_sync(0xffffffffu, rs1, 1);
        rs1 += __shfl_xor_sync(0xffffffffu, rs1, 2);
        l0 = l0 * al0 + rs0; m0r = mn0;
        l1 = l1 * al1 + rs1; m1r = mn1;
#pragma unroll
        for (int nb = 0; nb < 8; nb++) {
            o[nb][0] *= al0; o[nb][1] *= al0;
            o[nb][2] *= al1; o[nb][3] *= al1;
        }

        // ---- O += P V (3-term split), V transposed in smem ----
        const uint32_t vbase = kbase + 2 * AT_TILE;
#pragma unroll
        for (int j = 0; j < 4; j++) {
#pragma unroll
            for (int np = 0; np < 4; np++) {
                uint32_t ba = vbase + (np * 16 + brow) * AT_STRIDE + j * 32 + bkof;
                uint32_t bh2[4], bl2[4];
                LDSM4(bh2, ba);
                LDSM4(bl2, ba + AT_TILE);
                mma16816(o[2 * np], pah[j], bh2);
                mma16816(o[2 * np], pah[j], bl2);
                mma16816(o[2 * np], pal[j], bh2);
                mma16816(o[2 * np + 1], pah[j], bh2 + 2);
                mma16816(o[2 * np + 1], pah[j], bl2 + 2);
                mma16816(o[2 * np + 1], pal[j], bh2 + 2);
            }
        }
        __syncthreads();
    }

    // ---- fused epilogue: normalize + hi/lo split to [b][t][h*64] bf16 ----
    float i0 = (l0 > 0.f) ? (1.f / l0) : 0.f;
    float i1 = (l1 > 0.f) ? (1.f / l1) : 0.f;
    const int qr0 = q0 + wid * 16 + g, qr1 = qr0 + 8;
#pragma unroll
    for (int nb = 0; nb < 8; nb++) {
        int cc = h * DH_ + nb * 8 + tig * 2;
        float p0 = o[nb][0] * i0, p1 = o[nb][1] * i0;
        float p2 = o[nb][2] * i1, p3 = o[nb][3] * i1;
        uint32_t u0 = pack_bf2(p0, p1), u1 = pack_bf2(p2, p3);
        size_t i0x = (((size_t)b * T_ + qr0) * D_ + cc) >> 1;
        size_t i1x = (((size_t)b * T_ + qr1) * D_ + cc) >> 1;
        ((uint32_t*)Ohi)[i0x] = u0;
        ((uint32_t*)Olo)[i0x] = pack_res(u0, p0, p1);
        ((uint32_t*)Ohi)[i1x] = u1;
        ((uint32_t*)Olo)[i1x] = pack_res(u1, p2, p3);
    }
#undef LOAD_KV
}

// ---------------- launcher ----------------
extern "C" void kernel_launch(void* const* d_in, const int* in_sizes, int n_in,
                              void* d_out, int out_size) {
    const float* x    = (const float*)d_in[0];
    const float* ln_g = (const float*)d_in[1];
    const float* ln_b = (const float*)d_in[2];
    const float* Wq   = (const float*)d_in[3];
    const float* bq   = (const float*)d_in[4];
    const float* Wk   = (const float*)d_in[5];
    const float* bk   = (const float*)d_in[6];
    const float* Wv   = (const float*)d_in[7];
    const float* bv   = (const float*)d_in[8];
    const float* Wo   = (const float*)d_in[9];
    const float* bo   = (const float*)d_in[10];
    const int*  lens  = (const int*)d_in[13];
    float* out = (float*)d_out;

    float *q_, *k_, *v_;
    __nv_bfloat16 *ahi, *alo, *whi, *wlo, *qh, *ql, *kh, *kl, *vth, *vtl;
    cudaGetSymbolAddress((void**)&q_, g_q);
    cudaGetSymbolAddress((void**)&k_, g_k);
    cudaGetSymbolAddress((void**)&v_, g_v);
    cudaGetSymbolAddress((void**)&ahi, g_ahi);
    cudaGetSymbolAddress((void**)&alo, g_alo);
    cudaGetSymbolAddress((void**)&whi, g_whi);
    cudaGetSymbolAddress((void**)&wlo, g_wlo);
    cudaGetSymbolAddress((void**)&qh, g_qh);
    cudaGetSymbolAddress((void**)&ql, g_ql);
    cudaGetSymbolAddress((void**)&kh, g_kh);
    cudaGetSymbolAddress((void**)&kl, g_kl);
    cudaGetSymbolAddress((void**)&vth, g_vth);
    cudaGetSymbolAddress((void**)&vtl, g_vtl);

    cudaFuncSetAttribute(gemm_qkv_kernel, cudaFuncAttributeMaxDynamicSharedMemorySize, GEMM_SMEM);
    cudaFuncSetAttribute(gemm_mma_kernel, cudaFuncAttributeMaxDynamicSharedMemorySize, GEMM_SMEM);
    cudaFuncSetAttribute(attn_mma_kernel, cudaFuncAttributeMaxDynamicSharedMemorySize, ATT_SMEM);

    // LN fused with split
    ln_split_kernel<<<ROWS_, 256>>>(x, ln_g, ln_b, ahi, alo);

    // W^T segments: Q->rows[0,1024), K->rows[1024,2048), V->rows[2048,3072)
    const dim3 tg(32, 32), tb(32, 8);
    transpose_split_kernel<<<tg, tb>>>(Wq, whi, wlo);
    transpose_split_kernel<<<tg, tb>>>(Wk, whi + (size_t)GK_ * GK_, wlo + (size_t)GK_ * GK_);
    transpose_split_kernel<<<tg, tb>>>(Wv, whi + (size_t)2 * GK_ * GK_, wlo + (size_t)2 * GK_ * GK_);

    // fused QKV projection: 12 x 64 CTAs of 128x256
    gemm_qkv_kernel<<<dim3(12, 64), 256, GEMM_SMEM>>>(ahi, alo, whi, wlo,
                                                      bq, bk, bv, q_, k_, v_);

    rope_split_kernel<<<(N_ * T_ * H_ * 32) / 256, 256>>>(q_, k_, qh, ql, kh, kl);
    v_split_T_kernel<<<dim3(T_ / 32, DH_ / 32, N_ * H_), dim3(32, 8)>>>(v_, vth, vtl);

    // attention writes hi/lo split output directly
    attn_mma_kernel<<<dim3(T_ / 128, H_, N_), 256, ATT_SMEM>>>(qh, ql, kh, kl, vth, vtl, lens, ahi, alo);

    // Wo^T into segment 0; O-projection: 4 x 64 CTAs of 128x256
    transpose_split_kernel<<<tg, tb>>>(Wo, whi, wlo);
    gemm_mma_kernel<<<dim3(4, 64), 256, GEMM_SMEM>>>(ahi, alo, whi, wlo, bo, out);
}